// round 11
// baseline (speedup 1.0000x reference)
#include <cuda_runtime.h>
#include <cstdint>

#define NB   64
#define NT   1024
#define NIN  256
#define NH   512
#define NTHB 512     // step kernel threads
#define NCTA 64      // 2 super-groups x 32 col-groups (each CTA: 2 batch groups)
#define NBG  4       // batch groups total
#define NCG  32      // col groups (producers) per batch group

#define RB 20        // red per-col stride (floats)
#define RC 320       // red per-kt stride (16*RB)

// smem floats: wd 16384 (64KB u64) + frsA 8192 + frsB 8192 + red 5120
#define OFF_FRA 16384
#define OFF_FRB (16384 + 8192)
#define OFF_RED (16384 + 16384)
#define SMEM_FLOATS (OFF_RED + 16 * RC)
#define SMEM_BYTES  (SMEM_FLOATS * 4)     // 151552 B

// ---------------- device globals (scratch; no allocations allowed) ----------
// one flag per 128B L2 line
__device__ unsigned g_flags2[NBG][NCG][32];
// fr state: [buf][group][k][16 batches]
__device__ float    g_fr2[2][NBG][NH][16];

__global__ void init_kernel() {
    int i = blockIdx.x * blockDim.x + threadIdx.x;   // 4096 words
    ((unsigned*)g_flags2)[i] = 0u;
}

// ---------------- helpers -----------------------------------------------------
__device__ __forceinline__ uint64_t pk2(float x, float y) {
    uint64_t d; asm("mov.b64 %0, {%1, %2};" : "=l"(d) : "f"(x), "f"(y)); return d;
}
__device__ __forceinline__ void upk2(uint64_t d, float& x, float& y) {
    asm("mov.b64 {%0, %1}, %2;" : "=f"(x), "=f"(y) : "l"(d));
}
__device__ __forceinline__ uint64_t fma2(uint64_t a, uint64_t b, uint64_t c) {
    uint64_t d; asm("fma.rn.f32x2 %0, %1, %2, %3;" : "=l"(d) : "l"(a), "l"(b), "l"(c)); return d;
}
__device__ __forceinline__ unsigned ld_acq(const unsigned* p) {
    unsigned v;
    asm volatile("ld.acquire.gpu.global.u32 %0, [%1];" : "=r"(v) : "l"(p) : "memory");
    return v;
}
__device__ __forceinline__ void st_rel(unsigned* p, unsigned v) {
    asm volatile("st.release.gpu.global.u32 [%0], %1;" :: "l"(p), "r"(v) : "memory");
}
__device__ __forceinline__ float4 ldcg_v4(const float4* p) {
    float4 v;
    asm volatile("ld.global.cg.v4.f32 {%0, %1, %2, %3}, [%4];"
                 : "=f"(v.x), "=f"(v.y), "=f"(v.z), "=f"(v.w) : "l"(p) : "memory");
    return v;
}

// ---------------- Phase A: v_in = x @ W_in + b_in -> d_out (FFMA2) -----------
#define BM 64
#define BN 64
#define BK 16

__global__ __launch_bounds__(256) void gemm_vin(const float* __restrict__ A,
                                                const float* __restrict__ Bm,
                                                const float* __restrict__ bias,
                                                float* __restrict__ C) {
    __shared__ float    As[BK][BM + 4];
    __shared__ uint64_t Bs2[BK][BN / 2];      // {n,n+1} pairs
    const int tid = threadIdx.x;
    const int m0 = blockIdx.y * BM;
    const int n0 = blockIdx.x * BN;
    const int tx = tid & 15;     // 4 cols = 2 pairs
    const int ty = tid >> 4;     // 4 rows

    uint64_t acc[4][2];
#pragma unroll
    for (int i = 0; i < 4; ++i) { acc[i][0] = 0; acc[i][1] = 0; }

    for (int k0 = 0; k0 < NIN; k0 += BK) {
#pragma unroll
        for (int i = tid; i < BM * BK / 4; i += 256) {
            int m = i >> 2, kq = i & 3;
            float4 v = *(const float4*)(A + (long)(m0 + m) * NIN + k0 + kq * 4);
            As[kq * 4 + 0][m] = v.x;
            As[kq * 4 + 1][m] = v.y;
            As[kq * 4 + 2][m] = v.z;
            As[kq * 4 + 3][m] = v.w;
        }
#pragma unroll
        for (int i = tid; i < BK * BN / 4; i += 256) {
            int kk = i >> 4, nq = i & 15;
            float4 v = *(const float4*)(Bm + (long)(k0 + kk) * NH + n0 + nq * 4);
            Bs2[kk][nq * 2 + 0] = pk2(v.x, v.y);
            Bs2[kk][nq * 2 + 1] = pk2(v.z, v.w);
        }
        __syncthreads();

#pragma unroll
        for (int kk = 0; kk < BK; ++kk) {
            float4 a4 = *(const float4*)(&As[kk][ty * 4]);
            ulonglong2 bp = *(const ulonglong2*)(&Bs2[kk][tx * 2]);
            uint64_t ad0 = pk2(a4.x, a4.x);
            uint64_t ad1 = pk2(a4.y, a4.y);
            uint64_t ad2 = pk2(a4.z, a4.z);
            uint64_t ad3 = pk2(a4.w, a4.w);
            acc[0][0] = fma2(ad0, bp.x, acc[0][0]);
            acc[0][1] = fma2(ad0, bp.y, acc[0][1]);
            acc[1][0] = fma2(ad1, bp.x, acc[1][0]);
            acc[1][1] = fma2(ad1, bp.y, acc[1][1]);
            acc[2][0] = fma2(ad2, bp.x, acc[2][0]);
            acc[2][1] = fma2(ad2, bp.y, acc[2][1]);
            acc[3][0] = fma2(ad3, bp.x, acc[3][0]);
            acc[3][1] = fma2(ad3, bp.y, acc[3][1]);
        }
        __syncthreads();
    }

#pragma unroll
    for (int i = 0; i < 4; ++i) {
        const int m = m0 + ty * 4 + i;
        const int n = n0 + tx * 4;
        float c0, c1, c2, c3;
        upk2(acc[i][0], c0, c1);
        upk2(acc[i][1], c2, c3);
        float4 o;
        o.x = c0 + bias[n + 0];
        o.y = c1 + bias[n + 1];
        o.z = c2 + bias[n + 2];
        o.w = c3 + bias[n + 3];
        *(float4*)(C + (long)m * NH + n) = o;
    }
}

// ---------------- Phase B: persistent recurrent kernel ----------------------
// 64 CTAs = 2 super-groups x 32 col-groups; each CTA handles TWO batch groups
// (2s, 2s+1) over the same 16 columns (shared W in SMEM). Segments A and B
// run back-to-back each step: while B computes, A's L2 exchange propagates,
// so A's poll at t+1 hits already-set flags (exchange off the critical path).
// Protocol identical to R10 (acquire poll / release flag / volatile staging).

__global__ __launch_bounds__(NTHB, 1) void step_kernel(
    const float* __restrict__ W_hid,
    const float* __restrict__ b_hid,
    const float* __restrict__ alpha,
    const float* __restrict__ init_state,
    float* __restrict__ out) {
    extern __shared__ float sh[];
    uint64_t* wd   = (uint64_t*)sh;       // [512][16] u64: wd[k*16+c] = {w,w}
    float*    frsA = sh + OFF_FRA;        // [16 kt][32 k][16 b]
    float*    frsB = sh + OFF_FRB;
    float*    red  = sh + OFF_RED;        // [16 kt][16 c][RB]

    const int tid  = threadIdx.x;
    const int sg   = blockIdx.x >> 5;     // super group 0..1
    const int cgrp = blockIdx.x & 31;     // 0..31
    const int gA   = sg * 2;
    const int gB   = sg * 2 + 1;
    const int B0A  = gA * 16;
    const int B0B  = gB * 16;
    const int C0   = cgrp * 16;

    // compute roles
    const int kt   = tid >> 5;            // 0..15 (32 k each)
    const int lane = tid & 31;
    const int bg   = (tid >> 3) & 3;      // 0..3
    const int cg   = tid & 7;             // 0..7
    // fold roles (tid < 256)
    const int ec = tid & 15;
    const int eb = (tid >> 4) & 15;
    const int gc = C0 + ec;

    // ---- one-time: W slice as duplicated pairs ----
    for (int i = tid; i < NH * 16; i += NTHB) {
        int k = i >> 4, c = i & 15;
        float w = W_hid[(long)k * NH + C0 + c];
        wd[i] = pk2(w, w);
    }

    // ---- warp-local fr(0) slices for both groups ----
    {
#pragma unroll
        for (int j = 0; j < 4; ++j) {
            int fidx = j * 32 + lane;
            int kl = fidx >> 2, q = fidx & 3;
            int k = kt * 32 + kl;
            float4 va, vb;
            va.x = fmaxf(init_state[(long)(B0A + q * 4 + 0) * NH + k], 0.f);
            va.y = fmaxf(init_state[(long)(B0A + q * 4 + 1) * NH + k], 0.f);
            va.z = fmaxf(init_state[(long)(B0A + q * 4 + 2) * NH + k], 0.f);
            va.w = fmaxf(init_state[(long)(B0A + q * 4 + 3) * NH + k], 0.f);
            vb.x = fmaxf(init_state[(long)(B0B + q * 4 + 0) * NH + k], 0.f);
            vb.y = fmaxf(init_state[(long)(B0B + q * 4 + 1) * NH + k], 0.f);
            vb.z = fmaxf(init_state[(long)(B0B + q * 4 + 2) * NH + k], 0.f);
            vb.w = fmaxf(init_state[(long)(B0B + q * 4 + 3) * NH + k], 0.f);
            *(float4*)(frsA + kt * 512 + fidx * 4) = va;
            *(float4*)(frsB + kt * 512 + fidx * 4) = vb;
        }
    }

    float vA = 0.f, vB = 0.f, al = 0.f, bh = 0.f, oma = 0.f;
    if (tid < 256) {
        vA  = init_state[(long)(B0A + eb) * NH + gc];
        vB  = init_state[(long)(B0B + eb) * NH + gc];
        al  = alpha[gc];
        bh  = b_hid[gc];
        oma = 1.f - al;
    }
    __syncthreads();

    const uint64_t* wp0 = wd + (kt * 32) * 16 + cg * 2;

    // one segment: poll+stage, compute, fold group `grp`
    auto segment = [&](int t, int grp, int B0g, float* frsG, float& vG) {
        const long  oidx = ((long)(B0g + eb) * NT + (t - 1)) * NH + gc;
        float vin = 0.f;
        if (tid < 256) vin = out[oidx];               // prefetch

        if (t >= 2) {
            const unsigned tgt = (unsigned)(t - 1);
            const unsigned* fA = &g_flags2[grp][2 * kt][0];
            const unsigned* fB = &g_flags2[grp][2 * kt + 1][0];
            if (lane == 0) { while (ld_acq(fA) < tgt) { } }
            if (lane == 1) { while (ld_acq(fB) < tgt) { } }
            __syncwarp();

            const float* src = &g_fr2[(t - 1) & 1][grp][kt * 32][0];
            float*       dst = frsG + kt * 512;
#pragma unroll
            for (int j = 0; j < 4; ++j) {
                int fidx = j * 32 + lane;
                float4 vv = ldcg_v4((const float4*)src + fidx);
                *(float4*)(dst + fidx * 4) = vv;
            }
            __syncwarp();
        }

        // FFMA2 GEMM over K slice
        const float* fp0 = frsG + kt * 512 + bg * 4;
        uint64_t a00 = 0, a10 = 0, a01 = 0, a11 = 0;
#pragma unroll
        for (int kk = 0; kk < 32; ++kk) {
            ulonglong2 fv = *(const ulonglong2*)(fp0 + kk * 16);
            ulonglong2 wv = *(const ulonglong2*)(wp0 + kk * 16);
            a00 = fma2(fv.x, wv.x, a00);
            a10 = fma2(fv.y, wv.x, a10);
            a01 = fma2(fv.x, wv.y, a01);
            a11 = fma2(fv.y, wv.y, a11);
        }

        // publish kt-partials
        {
            float* rp = red + kt * RC + (cg * 2) * RB + bg * 4;
            ulonglong2 s0; s0.x = a00; s0.y = a10;
            ulonglong2 s1; s1.x = a01; s1.y = a11;
            *(ulonglong2*)rp        = s0;
            *(ulonglong2*)(rp + RB) = s1;
        }
        __syncthreads();

        // fold + leaky update
        if (tid < 256) {
            const float* rr = red + ec * RB + eb;
            float s0 = rr[0 * RC]  + rr[1 * RC];
            float s1 = rr[2 * RC]  + rr[3 * RC];
            float s2 = rr[4 * RC]  + rr[5 * RC];
            float s3 = rr[6 * RC]  + rr[7 * RC];
            float s4 = rr[8 * RC]  + rr[9 * RC];
            float s5 = rr[10 * RC] + rr[11 * RC];
            float s6 = rr[12 * RC] + rr[13 * RC];
            float s7 = rr[14 * RC] + rr[15 * RC];
            float s  = ((s0 + s1) + (s2 + s3)) + ((s4 + s5) + (s6 + s7));

            vG = oma * vG + al * (s + bh + vin);
            const float fr = fmaxf(vG, 0.f);
            __stcg(&g_fr2[t & 1][grp][gc][eb], fr);
            out[oidx] = fr;
            __threadfence();
        }
        __syncthreads();      // red WAR (next segment reuses) + stores fenced

        if (t < NT && tid == 0) {
            st_rel(&g_flags2[grp][cgrp][0], (unsigned)t);
        }
    };

    for (int t = 1; t <= NT; ++t) {
        segment(t, gA, B0A, frsA, vA);   // A's exchange hides under B
        segment(t, gB, B0B, frsB, vB);   // B's exchange hides under next A
    }
}

// ---------------- launch ----------------------------------------------------
extern "C" void kernel_launch(void* const* d_in, const int* in_sizes, int n_in,
                              void* d_out, int out_size) {
    const float* x     = (const float*)d_in[0];
    const float* init  = (const float*)d_in[1];
    const float* W_in  = (const float*)d_in[2];
    const float* b_in  = (const float*)d_in[3];
    const float* W_hid = (const float*)d_in[4];
    const float* b_hid = (const float*)d_in[5];
    const float* alpha = (const float*)d_in[6];
    float* out = (float*)d_out;

    cudaFuncSetAttribute(step_kernel,
                         cudaFuncAttributeMaxDynamicSharedMemorySize, SMEM_BYTES);

    init_kernel<<<8, 512>>>();             // zero flag words every replay

    dim3 grid(NH / BN, (NB * NT) / BM);    // (8, 1024)
    gemm_vin<<<grid, 256>>>(x, W_in, b_in, out);

    step_kernel<<<NCTA, NTHB, SMEM_BYTES>>>(W_hid, b_hid, alpha, init, out);
}

// round 12
// speedup vs baseline: 1.9130x; 1.9130x over previous
#include <cuda_runtime.h>
#include <cstdint>

#define NB    64
#define NT    1024
#define NIN   256
#define NH    512
#define NTHB  512
#define CLU   8                   // CTAs per cluster (col blocks)
#define NCLUS 16                  // clusters (batch groups, 4 batches each)
#define NCTA  (NCLUS * CLU)       // 128

// SMEM float offsets
#define OFF_F0  32768             // wsm = [0, 32768)  : [512][64] f32 = 128KB
#define OFF_F1  (32768 + 2048)    // frs bufs: [512][4] f32 = 8KB each
#define OFF_RED (32768 + 4096)    // red: [16][288] floats
#define RKT     288               // red per-kt stride (4 * 72)
#define RBS     72                // red per-batch stride (72 mod 32 = 8 -> conflict-free fold)
#define SMEM_FLOATS (OFF_RED + 16 * RKT)
#define SMEM_BYTES  (SMEM_FLOATS * 4)     // 165,888 B
#define TXBYTES 8192u             // 8 CTAs x 64 cols x 4 b x 4 B per step

// ---------------- helpers -----------------------------------------------------
__device__ __forceinline__ uint64_t pk2(float x, float y) {
    uint64_t d; asm("mov.b64 %0, {%1, %2};" : "=l"(d) : "f"(x), "f"(y)); return d;
}
__device__ __forceinline__ void upk2(uint64_t d, float& x, float& y) {
    asm("mov.b64 {%0, %1}, %2;" : "=f"(x), "=f"(y) : "l"(d));
}
__device__ __forceinline__ uint64_t fma2(uint64_t a, uint64_t b, uint64_t c) {
    uint64_t d; asm("fma.rn.f32x2 %0, %1, %2, %3;" : "=l"(d) : "l"(a), "l"(b), "l"(c)); return d;
}
__device__ __forceinline__ uint32_t sm_u32(const void* p) {
    return (uint32_t)__cvta_generic_to_shared(p);
}

#define MBAR_INIT(addr, cnt) \
    asm volatile("mbarrier.init.shared.b64 [%0], %1;" :: "r"(addr), "r"(cnt) : "memory")
// arrive(1) + add tx expectation for the CURRENT phase
#define ARRIVE_EXPECT(addr, tx) \
    asm volatile("mbarrier.arrive.expect_tx.shared.b64 _, [%0], %1;" :: "r"(addr), "r"(tx) : "memory")
// acquire parity wait (HW sleep)
#define WAITP(addr, ph) do {                                                    \
    uint32_t _done;                                                             \
    do {                                                                        \
        asm volatile("{\n\t.reg .pred p;\n\t"                                   \
            "mbarrier.try_wait.parity.acquire.cta.shared::cta.b64 p, [%1], %2, 0x989680;\n\t" \
            "selp.b32 %0, 1, 0, p;\n\t}"                                        \
            : "=r"(_done) : "r"(addr), "r"(ph) : "memory");                     \
    } while (!_done);                                                           \
} while (0)
// 16B remote SMEM store, completion tracked by remote mbarrier (no fence needed)
#define ST_ASYNC16(raddr, v0, v1, rmbar) \
    asm volatile("st.async.weak.shared::cluster.mbarrier::complete_tx::bytes.v2.b64 " \
                 "[%0], {%1, %2}, [%3];" :: "r"(raddr), "l"(v0), "l"(v1), "r"(rmbar) : "memory")
#define MAPA(dst, src, r) \
    asm volatile("mapa.shared::cluster.u32 %0, %1, %2;" : "=r"(dst) : "r"(src), "r"(r))
#define CLUSTER_SYNC_() do {                                          \
    asm volatile("barrier.cluster.arrive.aligned;" ::: "memory");     \
    asm volatile("barrier.cluster.wait.aligned;" ::: "memory");       \
} while (0)

// ---------------- Phase A: v_in = x @ W_in + b_in -> d_out (FFMA2) -----------
#define BM 64
#define BN 64
#define BK 16

__global__ __launch_bounds__(256) void gemm_vin(const float* __restrict__ A,
                                                const float* __restrict__ Bm,
                                                const float* __restrict__ bias,
                                                float* __restrict__ C) {
    __shared__ float    As[BK][BM + 4];
    __shared__ uint64_t Bs2[BK][BN / 2];
    const int tid = threadIdx.x;
    const int m0 = blockIdx.y * BM;
    const int n0 = blockIdx.x * BN;
    const int tx = tid & 15;
    const int ty = tid >> 4;

    uint64_t acc[4][2];
#pragma unroll
    for (int i = 0; i < 4; ++i) { acc[i][0] = 0; acc[i][1] = 0; }

    for (int k0 = 0; k0 < NIN; k0 += BK) {
#pragma unroll
        for (int i = tid; i < BM * BK / 4; i += 256) {
            int m = i >> 2, kq = i & 3;
            float4 v = *(const float4*)(A + (long)(m0 + m) * NIN + k0 + kq * 4);
            As[kq * 4 + 0][m] = v.x;
            As[kq * 4 + 1][m] = v.y;
            As[kq * 4 + 2][m] = v.z;
            As[kq * 4 + 3][m] = v.w;
        }
#pragma unroll
        for (int i = tid; i < BK * BN / 4; i += 256) {
            int kk = i >> 4, nq = i & 15;
            float4 v = *(const float4*)(Bm + (long)(k0 + kk) * NH + n0 + nq * 4);
            Bs2[kk][nq * 2 + 0] = pk2(v.x, v.y);
            Bs2[kk][nq * 2 + 1] = pk2(v.z, v.w);
        }
        __syncthreads();

#pragma unroll
        for (int kk = 0; kk < BK; ++kk) {
            float4 a4 = *(const float4*)(&As[kk][ty * 4]);
            ulonglong2 bp = *(const ulonglong2*)(&Bs2[kk][tx * 2]);
            uint64_t ad0 = pk2(a4.x, a4.x);
            uint64_t ad1 = pk2(a4.y, a4.y);
            uint64_t ad2 = pk2(a4.z, a4.z);
            uint64_t ad3 = pk2(a4.w, a4.w);
            acc[0][0] = fma2(ad0, bp.x, acc[0][0]);
            acc[0][1] = fma2(ad0, bp.y, acc[0][1]);
            acc[1][0] = fma2(ad1, bp.x, acc[1][0]);
            acc[1][1] = fma2(ad1, bp.y, acc[1][1]);
            acc[2][0] = fma2(ad2, bp.x, acc[2][0]);
            acc[2][1] = fma2(ad2, bp.y, acc[2][1]);
            acc[3][0] = fma2(ad3, bp.x, acc[3][0]);
            acc[3][1] = fma2(ad3, bp.y, acc[3][1]);
        }
        __syncthreads();
    }

#pragma unroll
    for (int i = 0; i < 4; ++i) {
        const int m = m0 + ty * 4 + i;
        const int n = n0 + tx * 4;
        float c0, c1, c2, c3;
        upk2(acc[i][0], c0, c1);
        upk2(acc[i][1], c2, c3);
        float4 o;
        o.x = c0 + bias[n + 0];
        o.y = c1 + bias[n + 1];
        o.z = c2 + bias[n + 2];
        o.w = c3 + bias[n + 3];
        *(float4*)(C + (long)m * NH + n) = o;
    }
}

// ---------------- Phase B: persistent recurrent kernel (st.async clusters) --
// 16 clusters x 8 CTAs; CTA = (batch group, 4 batches) x (64 cols).
// fr(t) delivered into every peer's SMEM via st.async + mbarrier tx-count:
// no fences, no flags, no staging. Double-buffered frs + 2 mbarriers.
// Phase protocol: each CTA arms its own bar with arrive(1)+expect_tx(8192)
// at startup (phase 0) and re-arms immediately after each wait (phase p+1).
// Causality: a peer's phase-(p+1) sends require our phase-p send, which is
// after our wait+re-arm -> expect is always registered before tx arrives.
// WAR: peer writes our frs[b] for step t only after all fr(t-1) sends, which
// are after every CTA finished computing on frs[b] at step t-1.

__global__ __launch_bounds__(NTHB, 1) __cluster_dims__(CLU, 1, 1)
void step_kernel(const float* __restrict__ W_hid,
                 const float* __restrict__ b_hid,
                 const float* __restrict__ alpha,
                 const float* __restrict__ init_state,
                 float* __restrict__ out) {
    extern __shared__ float sh[];
    float* wsm  = sh;                 // [512][64]
    float* red  = sh + OFF_RED;       // [16][288]
    __shared__ uint64_t bars[2];

    const int tid = threadIdx.x;
    uint32_t rank;
    asm("mov.u32 %0, %%cluster_ctarank;" : "=r"(rank));
    const int grp = blockIdx.x >> 3;      // 0..15
    const int B0  = grp * 4;
    const int C0  = (int)rank * 64;

    // compute roles: warp = kt (32 k each); lane: bp = batches {0,1}/{2,3}, cq = col quad
    const int kt   = tid >> 5;
    const int lane = tid & 31;
    const int bp   = lane >> 4;           // 0..1
    const int cq   = lane & 15;           // 0..15
    // fold roles (tid < 256): eb = batch, ec = col
    const int eb = tid & 3;
    const int ec = tid >> 2;              // 0..63
    const int gb = B0 + eb;
    const int gc = C0 + ec;

    // ---- one-time W slice: wsm[k][c] = W_hid[k][C0+c] ----
    for (int i = tid; i < NH * 16; i += NTHB) {
        int k = i >> 4, q = i & 15;
        *(float4*)(wsm + k * 64 + q * 4) =
            *(const float4*)(W_hid + (long)k * NH + C0 + q * 4);
    }

    // ---- barriers: count=1, arm phase 0 of both with full tx expectation ----
    const uint32_t bar0 = sm_u32(&bars[0]);
    const uint32_t bar1 = sm_u32(&bars[1]);
    if (tid == 0) {
        MBAR_INIT(bar0, 1);
        MBAR_INIT(bar1, 1);
        ARRIVE_EXPECT(bar0, TXBYTES);
        ARRIVE_EXPECT(bar1, TXBYTES);
    }

    // ---- frs buf0 = relu(init_state), full 512 cols for my 4 batches ----
    {
        float* f0 = sh + OFF_F0;
        for (int i = tid; i < NH * 4; i += NTHB) {
            int k = i >> 2, bb = i & 3;
            f0[i] = fmaxf(init_state[(long)(B0 + bb) * NH + k], 0.f);
        }
    }

    float v = 0.f, al = 0.f, bh = 0.f, oma = 0.f;
    if (tid < 256) {
        v   = init_state[(long)gb * NH + gc];
        al  = alpha[gc];
        bh  = b_hid[gc];
        oma = 1.f - al;
    }
    __syncthreads();
    CLUSTER_SYNC_();    // barriers + armed state visible before any st.async

    const float* wbase = wsm + kt * 32 * 64 + cq * 4;

    int ph0 = 0, ph1 = 0;
    for (int t = 1; t <= NT; ++t) {
        const int pb = (t - 1) & 1;       // buffer holding fr(t-1)
        const int b  = t & 1;             // buffer receiving fr(t)

        long  oidx = 0;
        float vin  = 0.f;
        if (tid < 256) {
            oidx = ((long)gb * NT + (t - 1)) * NH + gc;
            vin  = out[oidx];             // DRAM prefetch, rides under the wait
        }

        if (t >= 2) {
            const uint32_t ba = pb ? bar1 : bar0;
            const int ph = pb ? ph1 : ph0;
            WAITP(ba, ph);                // fr(t-1) fully landed in my SMEM
            if (pb) ph1 ^= 1; else ph0 ^= 1;
            if (tid == 0) ARRIVE_EXPECT(ba, TXBYTES);   // arm next phase
        }

        // ---- compute: per k: LDS.64 f-pair + LDS.128 w-quad + 4 FFMA2 ----
        const float* fbase = sh + (pb ? OFF_F1 : OFF_F0) + kt * 128 + bp * 2;
        uint64_t a00 = 0, a01 = 0, a10 = 0, a11 = 0;
#pragma unroll
        for (int kk = 0; kk < 32; ++kk) {
            float2     f2 = *(const float2*)(fbase + kk * 4);
            ulonglong2 wv = *(const ulonglong2*)(wbase + kk * 64);
            uint64_t fd0 = pk2(f2.x, f2.x);
            uint64_t fd1 = pk2(f2.y, f2.y);
            a00 = fma2(fd0, wv.x, a00);
            a01 = fma2(fd0, wv.y, a01);
            a10 = fma2(fd1, wv.x, a10);
            a11 = fma2(fd1, wv.y, a11);
        }

        // ---- publish kt-partials: red[kt][batch][col] ----
        {
            float* rp = red + kt * RKT + (2 * bp) * RBS + cq * 4;
            ulonglong2 s0; s0.x = a00; s0.y = a01;
            ulonglong2 s1; s1.x = a10; s1.y = a11;
            *(ulonglong2*)rp         = s0;
            *(ulonglong2*)(rp + RBS) = s1;
        }
        __syncthreads();

        // ---- fold + leaky update + scatter fr(t) to all 8 peers ----
        if (tid < 256) {
            const float* rr = red + eb * RBS + ec;
            float s0 = rr[0 * RKT]  + rr[1 * RKT];
            float s1 = rr[2 * RKT]  + rr[3 * RKT];
            float s2 = rr[4 * RKT]  + rr[5 * RKT];
            float s3 = rr[6 * RKT]  + rr[7 * RKT];
            float s4 = rr[8 * RKT]  + rr[9 * RKT];
            float s5 = rr[10 * RKT] + rr[11 * RKT];
            float s6 = rr[12 * RKT] + rr[13 * RKT];
            float s7 = rr[14 * RKT] + rr[15 * RKT];
            float s  = ((s0 + s1) + (s2 + s3)) + ((s4 + s5) + (s6 + s7));

            v = oma * v + al * (s + bh + vin);
            const float fr = fmaxf(v, 0.f);
            out[oidx] = fr;

            if (t < NT) {                  // nobody consumes fr(NT)
                // gather 4 batches of my col via width-4 shfl
                const float g0 = __shfl_sync(0xffffffffu, fr, 0, 4);
                const float g1 = __shfl_sync(0xffffffffu, fr, 1, 4);
                const float g2 = __shfl_sync(0xffffffffu, fr, 2, 4);
                const float g3 = __shfl_sync(0xffffffffu, fr, 3, 4);
                if (eb == 0) {
                    const uint64_t p01 = pk2(g0, g1);
                    const uint64_t p23 = pk2(g2, g3);
                    const uint32_t laddr = sm_u32(sh + (b ? OFF_F1 : OFF_F0) + gc * 4);
                    const uint32_t lbar  = b ? bar1 : bar0;
#pragma unroll
                    for (int r = 0; r < CLU; ++r) {
                        uint32_t ra, rb;
                        MAPA(ra, laddr, r);
                        MAPA(rb, lbar, r);
                        ST_ASYNC16(ra, p01, p23, rb);
                    }
                }
            }
        }
        __syncthreads();                   // red WAR for next step's publish
    }

    // no CTA exits while peers' st.async could still target its SMEM
    CLUSTER_SYNC_();
}

// ---------------- launch ----------------------------------------------------
extern "C" void kernel_launch(void* const* d_in, const int* in_sizes, int n_in,
                              void* d_out, int out_size) {
    const float* x     = (const float*)d_in[0];
    const float* init  = (const float*)d_in[1];
    const float* W_in  = (const float*)d_in[2];
    const float* b_in  = (const float*)d_in[3];
    const float* W_hid = (const float*)d_in[4];
    const float* b_hid = (const float*)d_in[5];
    const float* alpha = (const float*)d_in[6];
    float* out = (float*)d_out;

    cudaFuncSetAttribute(step_kernel,
                         cudaFuncAttributeMaxDynamicSharedMemorySize, SMEM_BYTES);

    dim3 grid(NH / BN, (NB * NT) / BM);    // (8, 1024)
    gemm_vin<<<grid, 256>>>(x, W_in, b_in, out);

    step_kernel<<<NCTA, NTHB, SMEM_BYTES>>>(W_hid, b_hid, alpha, init, out);
}

// round 13
// speedup vs baseline: 1.9212x; 1.0043x over previous
#include <cuda_runtime.h>
#include <cstdint>

#define NB    64
#define NT    1024
#define NIN   256
#define NH    512
#define NTHB  512
#define CLU   8                   // CTAs per cluster (col blocks)
#define NCLUS 16                  // clusters (batch groups, 4 batches each)
#define NCTA  (NCLUS * CLU)       // 128

// SMEM float offsets
#define OFF_F0  32768             // wsm = [0, 32768)  : [512][64] f32 = 128KB
#define OFF_F1  (32768 + 2048)    // frs bufs: [512][4] f32 = 8KB each
#define OFF_RED (32768 + 4096)    // red: [16][288] floats
#define RKT     288               // red per-kt stride (4 * 72)
#define RBS     72                // red per-batch stride
#define SMEM_FLOATS (OFF_RED + 16 * RKT)
#define SMEM_BYTES  (SMEM_FLOATS * 4)     // 165,888 B
#define TXPEER  1024u             // per-producer tx: 64 cols x 4 b x 4 B

// ---------------- helpers -----------------------------------------------------
__device__ __forceinline__ uint64_t pk2(float x, float y) {
    uint64_t d; asm("mov.b64 %0, {%1, %2};" : "=l"(d) : "f"(x), "f"(y)); return d;
}
__device__ __forceinline__ void upk2(uint64_t d, float& x, float& y) {
    asm("mov.b64 {%0, %1}, %2;" : "=f"(x), "=f"(y) : "l"(d));
}
__device__ __forceinline__ uint64_t fma2(uint64_t a, uint64_t b, uint64_t c) {
    uint64_t d; asm("fma.rn.f32x2 %0, %1, %2, %3;" : "=l"(d) : "l"(a), "l"(b), "l"(c)); return d;
}
__device__ __forceinline__ uint32_t sm_u32(const void* p) {
    return (uint32_t)__cvta_generic_to_shared(p);
}

#define MBAR_INIT(addr, cnt) \
    asm volatile("mbarrier.init.shared.b64 [%0], %1;" :: "r"(addr), "r"(cnt) : "memory")
#define ARRIVE_EXPECT(addr, tx) \
    asm volatile("mbarrier.arrive.expect_tx.shared.b64 _, [%0], %1;" :: "r"(addr), "r"(tx) : "memory")
#define WAITP(addr, ph) do {                                                    \
    uint32_t _done;                                                             \
    do {                                                                        \
        asm volatile("{\n\t.reg .pred p;\n\t"                                   \
            "mbarrier.try_wait.parity.acquire.cta.shared::cta.b64 p, [%1], %2, 0x989680;\n\t" \
            "selp.b32 %0, 1, 0, p;\n\t}"                                        \
            : "=r"(_done) : "r"(addr), "r"(ph) : "memory");                     \
    } while (!_done);                                                           \
} while (0)
#define ST_ASYNC16(raddr, v0, v1, rmbar) \
    asm volatile("st.async.weak.shared::cluster.mbarrier::complete_tx::bytes.v2.b64 " \
                 "[%0], {%1, %2}, [%3];" :: "r"(raddr), "l"(v0), "l"(v1), "r"(rmbar) : "memory")
#define MAPA(dst, src, r) \
    asm volatile("mapa.shared::cluster.u32 %0, %1, %2;" : "=r"(dst) : "r"(src), "r"(r))
#define CLUSTER_SYNC_() do {                                          \
    asm volatile("barrier.cluster.arrive.aligned;" ::: "memory");     \
    asm volatile("barrier.cluster.wait.aligned;" ::: "memory");       \
} while (0)

// ---------------- Phase A: v_in = x @ W_in + b_in -> d_out (FFMA2) -----------
#define BM 64
#define BN 64
#define BK 16

__global__ __launch_bounds__(256) void gemm_vin(const float* __restrict__ A,
                                                const float* __restrict__ Bm,
                                                const float* __restrict__ bias,
                                                float* __restrict__ C) {
    __shared__ float    As[BK][BM + 4];
    __shared__ uint64_t Bs2[BK][BN / 2];
    const int tid = threadIdx.x;
    const int m0 = blockIdx.y * BM;
    const int n0 = blockIdx.x * BN;
    const int tx = tid & 15;
    const int ty = tid >> 4;

    uint64_t acc[4][2];
#pragma unroll
    for (int i = 0; i < 4; ++i) { acc[i][0] = 0; acc[i][1] = 0; }

    for (int k0 = 0; k0 < NIN; k0 += BK) {
#pragma unroll
        for (int i = tid; i < BM * BK / 4; i += 256) {
            int m = i >> 2, kq = i & 3;
            float4 v = *(const float4*)(A + (long)(m0 + m) * NIN + k0 + kq * 4);
            As[kq * 4 + 0][m] = v.x;
            As[kq * 4 + 1][m] = v.y;
            As[kq * 4 + 2][m] = v.z;
            As[kq * 4 + 3][m] = v.w;
        }
#pragma unroll
        for (int i = tid; i < BK * BN / 4; i += 256) {
            int kk = i >> 4, nq = i & 15;
            float4 v = *(const float4*)(Bm + (long)(k0 + kk) * NH + n0 + nq * 4);
            Bs2[kk][nq * 2 + 0] = pk2(v.x, v.y);
            Bs2[kk][nq * 2 + 1] = pk2(v.z, v.w);
        }
        __syncthreads();

#pragma unroll
        for (int kk = 0; kk < BK; ++kk) {
            float4 a4 = *(const float4*)(&As[kk][ty * 4]);
            ulonglong2 bp = *(const ulonglong2*)(&Bs2[kk][tx * 2]);
            uint64_t ad0 = pk2(a4.x, a4.x);
            uint64_t ad1 = pk2(a4.y, a4.y);
            uint64_t ad2 = pk2(a4.z, a4.z);
            uint64_t ad3 = pk2(a4.w, a4.w);
            acc[0][0] = fma2(ad0, bp.x, acc[0][0]);
            acc[0][1] = fma2(ad0, bp.y, acc[0][1]);
            acc[1][0] = fma2(ad1, bp.x, acc[1][0]);
            acc[1][1] = fma2(ad1, bp.y, acc[1][1]);
            acc[2][0] = fma2(ad2, bp.x, acc[2][0]);
            acc[2][1] = fma2(ad2, bp.y, acc[2][1]);
            acc[3][0] = fma2(ad3, bp.x, acc[3][0]);
            acc[3][1] = fma2(ad3, bp.y, acc[3][1]);
        }
        __syncthreads();
    }

#pragma unroll
    for (int i = 0; i < 4; ++i) {
        const int m = m0 + ty * 4 + i;
        const int n = n0 + tx * 4;
        float c0, c1, c2, c3;
        upk2(acc[i][0], c0, c1);
        upk2(acc[i][1], c2, c3);
        float4 o;
        o.x = c0 + bias[n + 0];
        o.y = c1 + bias[n + 1];
        o.z = c2 + bias[n + 2];
        o.w = c3 + bias[n + 3];
        *(float4*)(C + (long)m * NH + n) = o;
    }
}

// ---------------- Phase B: persistent recurrent kernel (per-peer mbarriers) -
// 16 clusters x 8 CTAs; CTA = (4 batches) x (64 cols). fr(t) delivered into
// peers' SMEM via st.async, tx tracked by PER-PRODUCER barriers bars[buf][r]
// (expect 1KB each). Warp kt consumes k in [32kt,32kt+32) = producer r=kt>>1,
// so it waits only bars[pb][kt>>1] and starts computing as soon as that 1KB
// lands -> no cluster-wide max-coupling. Re-arm by even warp of each pair
// after its wait (2r+1 waits same already-completed parity: safe). Causality
// for re-arm vs next sends: peer's fr(t+2) sends require my fr(t+1) send,
// which is after all my step-(t+1) computes, after my step-t re-arm.

__global__ __launch_bounds__(NTHB, 1) __cluster_dims__(CLU, 1, 1)
void step_kernel(const float* __restrict__ W_hid,
                 const float* __restrict__ b_hid,
                 const float* __restrict__ alpha,
                 const float* __restrict__ init_state,
                 float* __restrict__ out) {
    extern __shared__ float sh[];
    float* wsm  = sh;                 // [512][64]
    float* red  = sh + OFF_RED;       // [16][288]
    __shared__ uint64_t bars[2][CLU]; // [buf][producer rank]

    const int tid = threadIdx.x;
    uint32_t rank;
    asm("mov.u32 %0, %%cluster_ctarank;" : "=r"(rank));
    const int grp = blockIdx.x >> 3;      // 0..15
    const int B0  = grp * 4;
    const int C0  = (int)rank * 64;

    const int kt   = tid >> 5;            // warp = k-slice
    const int lane = tid & 31;
    const int bp   = lane >> 4;           // batches {0,1} / {2,3}
    const int cq   = lane & 15;           // col quad
    const int myprod = kt >> 1;           // producer peer of my k-slice
    // fold roles (tid < 256)
    const int eb = tid & 3;
    const int ec = tid >> 2;              // 0..63
    const int gb = B0 + eb;
    const int gc = C0 + ec;

    // ---- one-time W slice ----
    for (int i = tid; i < NH * 16; i += NTHB) {
        int k = i >> 4, q = i & 15;
        *(float4*)(wsm + k * 64 + q * 4) =
            *(const float4*)(W_hid + (long)k * NH + C0 + q * 4);
    }

    // ---- barriers: 2 bufs x 8 producers, count=1, arm phase 0 w/ 1KB ----
    if (tid == 0) {
#pragma unroll
        for (int r = 0; r < CLU; ++r) {
            MBAR_INIT(sm_u32(&bars[0][r]), 1);
            MBAR_INIT(sm_u32(&bars[1][r]), 1);
            ARRIVE_EXPECT(sm_u32(&bars[0][r]), TXPEER);
            ARRIVE_EXPECT(sm_u32(&bars[1][r]), TXPEER);
        }
    }

    // ---- frs buf0 = relu(init_state) ----
    {
        float* f0 = sh + OFF_F0;
        for (int i = tid; i < NH * 4; i += NTHB) {
            int k = i >> 2, bb = i & 3;
            f0[i] = fmaxf(init_state[(long)(B0 + bb) * NH + k], 0.f);
        }
    }

    float v = 0.f, al = 0.f, bh = 0.f, oma = 0.f;
    if (tid < 256) {
        v   = init_state[(long)gb * NH + gc];
        al  = alpha[gc];
        bh  = b_hid[gc];
        oma = 1.f - al;
    }
    __syncthreads();
    CLUSTER_SYNC_();    // barriers + armed state visible before any st.async

    const float* wbase = wsm + kt * 32 * 64 + cq * 4;
    const uint32_t mybar0 = sm_u32(&bars[0][myprod]);
    const uint32_t mybar1 = sm_u32(&bars[1][myprod]);

    int ph0 = 0, ph1 = 0;
    for (int t = 1; t <= NT; ++t) {
        const int pb = (t - 1) & 1;       // buffer holding fr(t-1)
        const int b  = t & 1;             // buffer receiving fr(t)

        long  oidx = 0;
        float vin  = 0.f;
        if (tid < 256) {
            oidx = ((long)gb * NT + (t - 1)) * NH + gc;
            vin  = out[oidx];             // DRAM prefetch
        }

        if (t >= 2) {
            // per-warp wait: only my producer's 1KB must have landed
            const uint32_t ba = pb ? mybar1 : mybar0;
            const int ph = pb ? ph1 : ph0;
            WAITP(ba, ph);
            if (pb) ph1 ^= 1; else ph0 ^= 1;
            if ((kt & 1) == 0 && lane == 0) ARRIVE_EXPECT(ba, TXPEER);
        }

        // ---- compute: per k: LDS.64 f-pair + LDS.128 w-quad + 4 FFMA2 ----
        const float* fbase = sh + (pb ? OFF_F1 : OFF_F0) + kt * 128 + bp * 2;
        uint64_t a00 = 0, a01 = 0, a10 = 0, a11 = 0;
#pragma unroll
        for (int kk = 0; kk < 32; ++kk) {
            float2     f2 = *(const float2*)(fbase + kk * 4);
            ulonglong2 wv = *(const ulonglong2*)(wbase + kk * 64);
            uint64_t fd0 = pk2(f2.x, f2.x);
            uint64_t fd1 = pk2(f2.y, f2.y);
            a00 = fma2(fd0, wv.x, a00);
            a01 = fma2(fd0, wv.y, a01);
            a10 = fma2(fd1, wv.x, a10);
            a11 = fma2(fd1, wv.y, a11);
        }

        // ---- publish kt-partials ----
        {
            float* rp = red + kt * RKT + (2 * bp) * RBS + cq * 4;
            ulonglong2 s0; s0.x = a00; s0.y = a01;
            ulonglong2 s1; s1.x = a10; s1.y = a11;
            *(ulonglong2*)rp         = s0;
            *(ulonglong2*)(rp + RBS) = s1;
        }
        __syncthreads();

        // ---- fold + leaky update + scatter fr(t) ----
        if (tid < 256) {
            const float* rr = red + eb * RBS + ec;
            float s0 = rr[0 * RKT]  + rr[1 * RKT];
            float s1 = rr[2 * RKT]  + rr[3 * RKT];
            float s2 = rr[4 * RKT]  + rr[5 * RKT];
            float s3 = rr[6 * RKT]  + rr[7 * RKT];
            float s4 = rr[8 * RKT]  + rr[9 * RKT];
            float s5 = rr[10 * RKT] + rr[11 * RKT];
            float s6 = rr[12 * RKT] + rr[13 * RKT];
            float s7 = rr[14 * RKT] + rr[15 * RKT];
            float s  = ((s0 + s1) + (s2 + s3)) + ((s4 + s5) + (s6 + s7));

            v = oma * v + al * (s + bh + vin);
            const float fr = fmaxf(v, 0.f);

            if (t < NT) {                  // nobody consumes fr(NT)
                const float g0 = __shfl_sync(0xffffffffu, fr, 0, 4);
                const float g1 = __shfl_sync(0xffffffffu, fr, 1, 4);
                const float g2 = __shfl_sync(0xffffffffu, fr, 2, 4);
                const float g3 = __shfl_sync(0xffffffffu, fr, 3, 4);
                if (eb == 0) {
                    const uint64_t p01 = pk2(g0, g1);
                    const uint64_t p23 = pk2(g2, g3);
                    const uint32_t laddr = sm_u32(sh + (b ? OFF_F1 : OFF_F0) + gc * 4);
                    const uint32_t lbar  = sm_u32(&bars[b][rank]);  // my slot on peers
#pragma unroll
                    for (int i = 0; i < CLU; ++i) {
                        const uint32_t r = (rank + (uint32_t)i) & 7;  // staggered
                        uint32_t ra, rb;
                        MAPA(ra, laddr, r);
                        MAPA(rb, lbar, r);
                        ST_ASYNC16(ra, p01, p23, rb);
                    }
                }
            }
            out[oidx] = fr;                // after sends: off critical path
        }
        __syncthreads();                   // red WAR for next step's publish
    }

    CLUSTER_SYNC_();                       // guard exit vs in-flight st.async
}

// ---------------- launch ----------------------------------------------------
extern "C" void kernel_launch(void* const* d_in, const int* in_sizes, int n_in,
                              void* d_out, int out_size) {
    const float* x     = (const float*)d_in[0];
    const float* init  = (const float*)d_in[1];
    const float* W_in  = (const float*)d_in[2];
    const float* b_in  = (const float*)d_in[3];
    const float* W_hid = (const float*)d_in[4];
    const float* b_hid = (const float*)d_in[5];
    const float* alpha = (const float*)d_in[6];
    float* out = (float*)d_out;

    cudaFuncSetAttribute(step_kernel,
                         cudaFuncAttributeMaxDynamicSharedMemorySize, SMEM_BYTES);

    dim3 grid(NH / BN, (NB * NT) / BM);    // (8, 1024)
    gemm_vin<<<grid, 256>>>(x, W_in, b_in, out);

    step_kernel<<<NCTA, NTHB, SMEM_BYTES>>>(W_hid, b_hid, alpha, init, out);
}

// round 14
// speedup vs baseline: 2.1405x; 1.1141x over previous
#include <cuda_runtime.h>
#include <cstdint>

#define NB    64
#define NT    1024
#define NIN   256
#define NH    512
#define NTHB  512
#define CLU   8                   // CTAs per cluster (col blocks)
#define NCLUS 16                  // clusters (batch groups, 4 batches each)
#define NCTA  (NCLUS * CLU)       // 128

// SMEM float offsets (dynamic)
// frs bufs: [512 k][8] = dup-packed {b0,b0,b1,b1,b2,b2,b3,b3} -> 16KB each
#define OFF_F0  0
#define OFF_F1  4096
#define OFF_RED 8192              // red: [16 kt][4 b][72] floats
#define RKT     288               // per-kt stride (4*72)
#define RBS     72                // per-batch stride (conflict-free fold)
#define SMEM_FLOATS (OFF_RED + 16 * RKT)
#define SMEM_BYTES  (SMEM_FLOATS * 4)     // 51,200 B
#define TXPEER  2048u             // per-producer tx: 64 cols x 32 B

// ---------------- helpers -----------------------------------------------------
__device__ __forceinline__ uint64_t pk2(float x, float y) {
    uint64_t d; asm("mov.b64 %0, {%1, %2};" : "=l"(d) : "f"(x), "f"(y)); return d;
}
__device__ __forceinline__ void upk2(uint64_t d, float& x, float& y) {
    asm("mov.b64 {%0, %1}, %2;" : "=f"(x), "=f"(y) : "l"(d));
}
__device__ __forceinline__ uint64_t fma2(uint64_t a, uint64_t b, uint64_t c) {
    uint64_t d; asm("fma.rn.f32x2 %0, %1, %2, %3;" : "=l"(d) : "l"(a), "l"(b), "l"(c)); return d;
}
__device__ __forceinline__ uint32_t sm_u32(const void* p) {
    return (uint32_t)__cvta_generic_to_shared(p);
}

#define MBAR_INIT(addr, cnt) \
    asm volatile("mbarrier.init.shared.b64 [%0], %1;" :: "r"(addr), "r"(cnt) : "memory")
#define ARRIVE_EXPECT(addr, tx) \
    asm volatile("mbarrier.arrive.expect_tx.shared.b64 _, [%0], %1;" :: "r"(addr), "r"(tx) : "memory")
#define WAITP(addr, ph) do {                                                    \
    uint32_t _done;                                                             \
    do {                                                                        \
        asm volatile("{\n\t.reg .pred p;\n\t"                                   \
            "mbarrier.try_wait.parity.acquire.cta.shared::cta.b64 p, [%1], %2, 0x989680;\n\t" \
            "selp.b32 %0, 1, 0, p;\n\t}"                                        \
            : "=r"(_done) : "r"(addr), "r"(ph) : "memory");                     \
    } while (!_done);                                                           \
} while (0)
#define ST_ASYNC16(raddr, v0, v1, rmbar) \
    asm volatile("st.async.weak.shared::cluster.mbarrier::complete_tx::bytes.v2.b64 " \
                 "[%0], {%1, %2}, [%3];" :: "r"(raddr), "l"(v0), "l"(v1), "r"(rmbar) : "memory")
#define MAPA(dst, src, r) \
    asm volatile("mapa.shared::cluster.u32 %0, %1, %2;" : "=r"(dst) : "r"(src), "r"(r))
#define CLUSTER_SYNC_() do {                                          \
    asm volatile("barrier.cluster.arrive.aligned;" ::: "memory");     \
    asm volatile("barrier.cluster.wait.aligned;" ::: "memory");       \
} while (0)

// ---------------- Phase A: v_in = x @ W_in + b_in -> d_out (FFMA2) -----------
#define BM 64
#define BN 64
#define BK 16

__global__ __launch_bounds__(256) void gemm_vin(const float* __restrict__ A,
                                                const float* __restrict__ Bm,
                                                const float* __restrict__ bias,
                                                float* __restrict__ C) {
    __shared__ float    As[BK][BM + 4];
    __shared__ uint64_t Bs2[BK][BN / 2];
    const int tid = threadIdx.x;
    const int m0 = blockIdx.y * BM;
    const int n0 = blockIdx.x * BN;
    const int tx = tid & 15;
    const int ty = tid >> 4;

    uint64_t acc[4][2];
#pragma unroll
    for (int i = 0; i < 4; ++i) { acc[i][0] = 0; acc[i][1] = 0; }

    for (int k0 = 0; k0 < NIN; k0 += BK) {
#pragma unroll
        for (int i = tid; i < BM * BK / 4; i += 256) {
            int m = i >> 2, kq = i & 3;
            float4 v = *(const float4*)(A + (long)(m0 + m) * NIN + k0 + kq * 4);
            As[kq * 4 + 0][m] = v.x;
            As[kq * 4 + 1][m] = v.y;
            As[kq * 4 + 2][m] = v.z;
            As[kq * 4 + 3][m] = v.w;
        }
#pragma unroll
        for (int i = tid; i < BK * BN / 4; i += 256) {
            int kk = i >> 4, nq = i & 15;
            float4 v = *(const float4*)(Bm + (long)(k0 + kk) * NH + n0 + nq * 4);
            Bs2[kk][nq * 2 + 0] = pk2(v.x, v.y);
            Bs2[kk][nq * 2 + 1] = pk2(v.z, v.w);
        }
        __syncthreads();

#pragma unroll
        for (int kk = 0; kk < BK; ++kk) {
            float4 a4 = *(const float4*)(&As[kk][ty * 4]);
            ulonglong2 bp = *(const ulonglong2*)(&Bs2[kk][tx * 2]);
            uint64_t ad0 = pk2(a4.x, a4.x);
            uint64_t ad1 = pk2(a4.y, a4.y);
            uint64_t ad2 = pk2(a4.z, a4.z);
            uint64_t ad3 = pk2(a4.w, a4.w);
            acc[0][0] = fma2(ad0, bp.x, acc[0][0]);
            acc[0][1] = fma2(ad0, bp.y, acc[0][1]);
            acc[1][0] = fma2(ad1, bp.x, acc[1][0]);
            acc[1][1] = fma2(ad1, bp.y, acc[1][1]);
            acc[2][0] = fma2(ad2, bp.x, acc[2][0]);
            acc[2][1] = fma2(ad2, bp.y, acc[2][1]);
            acc[3][0] = fma2(ad3, bp.x, acc[3][0]);
            acc[3][1] = fma2(ad3, bp.y, acc[3][1]);
        }
        __syncthreads();
    }

#pragma unroll
    for (int i = 0; i < 4; ++i) {
        const int m = m0 + ty * 4 + i;
        const int n = n0 + tx * 4;
        float c0, c1, c2, c3;
        upk2(acc[i][0], c0, c1);
        upk2(acc[i][1], c2, c3);
        float4 o;
        o.x = c0 + bias[n + 0];
        o.y = c1 + bias[n + 1];
        o.z = c2 + bias[n + 2];
        o.w = c3 + bias[n + 3];
        *(float4*)(C + (long)m * NH + n) = o;
    }
}

// ---------------- Phase B: persistent recurrent kernel ----------------------
// 16 clusters x 8 CTAs; CTA = (4 batches) x (64 cols), 512 threads.
// W lives in REGISTERS: lane owns a col-pair x 32 k = 32 packed u64 (64 regs).
// fr is exchanged PRE-DUPLICATED ({f,f} pairs): consumer inner loop is
// 2 broadcast LDS.128 + 4 FFMA2 per k -- no MOVs, no W traffic.
// Per-producer mbarriers (expect 2KB each); warp kt waits only its producer.

__global__ __launch_bounds__(NTHB, 1) __cluster_dims__(CLU, 1, 1)
void step_kernel(const float* __restrict__ W_hid,
                 const float* __restrict__ b_hid,
                 const float* __restrict__ alpha,
                 const float* __restrict__ init_state,
                 float* __restrict__ out) {
    extern __shared__ float sh[];
    float* red = sh + OFF_RED;        // [16][288]
    __shared__ uint64_t bars[2][CLU]; // [buf][producer rank]

    const int tid = threadIdx.x;
    uint32_t rank;
    asm("mov.u32 %0, %%cluster_ctarank;" : "=r"(rank));
    const int grp = blockIdx.x >> 3;      // 0..15
    const int B0  = grp * 4;
    const int C0  = (int)rank * 64;

    const int kt   = tid >> 5;            // warp = k-slice (32 k)
    const int lane = tid & 31;            // lane = col-pair (cols 2l, 2l+1)
    const int myprod = kt >> 1;           // producer peer of my k-slice
    // fold roles (tid < 256)
    const int eb = tid & 3;
    const int ec = tid >> 2;              // 0..63
    const int gb = B0 + eb;
    const int gc = C0 + ec;

    // ---- one-time: W col-pair slice into registers ----
    uint64_t wreg[32];
#pragma unroll
    for (int kk = 0; kk < 32; ++kk) {
        float2 wv = *(const float2*)(W_hid + (long)(kt * 32 + kk) * NH + C0 + 2 * lane);
        wreg[kk] = pk2(wv.x, wv.y);
    }

    // ---- barriers: 2 bufs x 8 producers, count=1, arm phase 0 w/ 2KB ----
    if (tid == 0) {
#pragma unroll
        for (int r = 0; r < CLU; ++r) {
            MBAR_INIT(sm_u32(&bars[0][r]), 1);
            MBAR_INIT(sm_u32(&bars[1][r]), 1);
            ARRIVE_EXPECT(sm_u32(&bars[0][r]), TXPEER);
            ARRIVE_EXPECT(sm_u32(&bars[1][r]), TXPEER);
        }
    }

    // ---- frs buf0 = relu(init_state), dup-packed [k][b0b0b1b1b2b2b3b3] ----
    {
        float* f0 = sh + OFF_F0;
        for (int i = tid; i < NH * 8; i += NTHB) {
            int k = i >> 3, b = (i & 7) >> 1;
            f0[i] = fmaxf(init_state[(long)(B0 + b) * NH + k], 0.f);
        }
    }

    float v = 0.f, al = 0.f, bh = 0.f, oma = 0.f;
    if (tid < 256) {
        v   = init_state[(long)gb * NH + gc];
        al  = alpha[gc];
        bh  = b_hid[gc];
        oma = 1.f - al;
    }
    __syncthreads();
    CLUSTER_SYNC_();    // barriers + armed state visible before any st.async

    const uint32_t mybar0 = sm_u32(&bars[0][myprod]);
    const uint32_t mybar1 = sm_u32(&bars[1][myprod]);

    int ph0 = 0, ph1 = 0;
    for (int t = 1; t <= NT; ++t) {
        const int pb = (t - 1) & 1;       // buffer holding fr(t-1)
        const int b  = t & 1;             // buffer receiving fr(t)

        long  oidx = 0;
        float vin  = 0.f;
        if (tid < 256) {
            oidx = ((long)gb * NT + (t - 1)) * NH + gc;
            vin  = out[oidx];             // DRAM prefetch
        }

        if (t >= 2) {
            const uint32_t ba = pb ? mybar1 : mybar0;
            const int ph = pb ? ph1 : ph0;
            WAITP(ba, ph);                // my producer's 2KB landed
            if (pb) ph1 ^= 1; else ph0 ^= 1;
            if ((kt & 1) == 0 && lane == 0) ARRIVE_EXPECT(ba, TXPEER);
        }

        // ---- compute: per k: 2 broadcast LDS.128 + 4 FFMA2 (W in regs) ----
        const float* fbase = sh + (pb ? OFF_F1 : OFF_F0) + kt * 256;
        uint64_t a0 = 0, a1 = 0, a2 = 0, a3 = 0;
#pragma unroll
        for (int kk = 0; kk < 32; ++kk) {
            ulonglong2 fA = *(const ulonglong2*)(fbase + kk * 8);      // {b0,b0},{b1,b1}
            ulonglong2 fB = *(const ulonglong2*)(fbase + kk * 8 + 4);  // {b2,b2},{b3,b3}
            a0 = fma2(fA.x, wreg[kk], a0);
            a1 = fma2(fA.y, wreg[kk], a1);
            a2 = fma2(fB.x, wreg[kk], a2);
            a3 = fma2(fB.y, wreg[kk], a3);
        }

        // ---- publish kt-partials: red[kt][b][2*lane..2*lane+1] ----
        {
            float* rp = red + kt * RKT + 2 * lane;
            *(uint64_t*)(rp + 0 * RBS) = a0;
            *(uint64_t*)(rp + 1 * RBS) = a1;
            *(uint64_t*)(rp + 2 * RBS) = a2;
            *(uint64_t*)(rp + 3 * RBS) = a3;
        }
        __syncthreads();

        // ---- fold + leaky update + scatter fr(t) dup-packed ----
        if (tid < 256) {
            const float* rr = red + eb * RBS + ec;
            float s0 = rr[0 * RKT]  + rr[1 * RKT];
            float s1 = rr[2 * RKT]  + rr[3 * RKT];
            float s2 = rr[4 * RKT]  + rr[5 * RKT];
            float s3 = rr[6 * RKT]  + rr[7 * RKT];
            float s4 = rr[8 * RKT]  + rr[9 * RKT];
            float s5 = rr[10 * RKT] + rr[11 * RKT];
            float s6 = rr[12 * RKT] + rr[13 * RKT];
            float s7 = rr[14 * RKT] + rr[15 * RKT];
            float s  = ((s0 + s1) + (s2 + s3)) + ((s4 + s5) + (s6 + s7));

            v = oma * v + al * (s + bh + vin);
            const float fr = fmaxf(v, 0.f);

            if (t < NT) {                  // nobody consumes fr(NT)
                const float g0 = __shfl_sync(0xffffffffu, fr, 0, 4);
                const float g1 = __shfl_sync(0xffffffffu, fr, 1, 4);
                const float g2 = __shfl_sync(0xffffffffu, fr, 2, 4);
                const float g3 = __shfl_sync(0xffffffffu, fr, 3, 4);
                // eb==0 sends {b0,b0},{b1,b1}; eb==1 sends {b2,b2},{b3,b3}
                if (eb < 2) {
                    const uint64_t d0 = (eb == 0) ? pk2(g0, g0) : pk2(g2, g2);
                    const uint64_t d1 = (eb == 0) ? pk2(g1, g1) : pk2(g3, g3);
                    const uint32_t laddr =
                        sm_u32(sh + (b ? OFF_F1 : OFF_F0) + gc * 8 + eb * 4);
                    const uint32_t lbar = sm_u32(&bars[b][rank]);
#pragma unroll
                    for (int i = 0; i < CLU; ++i) {
                        const uint32_t r = (rank + (uint32_t)i) & 7;  // staggered
                        uint32_t ra, rb;
                        MAPA(ra, laddr, r);
                        MAPA(rb, lbar, r);
                        ST_ASYNC16(ra, d0, d1, rb);
                    }
                }
            }
            out[oidx] = fr;                // after sends: off critical path
        }
        __syncthreads();                   // red WAR for next step's publish
    }

    CLUSTER_SYNC_();                       // guard exit vs in-flight st.async
}

// ---------------- launch ----------------------------------------------------
extern "C" void kernel_launch(void* const* d_in, const int* in_sizes, int n_in,
                              void* d_out, int out_size) {
    const float* x     = (const float*)d_in[0];
    const float* init  = (const float*)d_in[1];
    const float* W_in  = (const float*)d_in[2];
    const float* b_in  = (const float*)d_in[3];
    const float* W_hid = (const float*)d_in[4];
    const float* b_hid = (const float*)d_in[5];
    const float* alpha = (const float*)d_in[6];
    float* out = (float*)d_out;

    cudaFuncSetAttribute(step_kernel,
                         cudaFuncAttributeMaxDynamicSharedMemorySize, SMEM_BYTES);

    dim3 grid(NH / BN, (NB * NT) / BM);    // (8, 1024)
    gemm_vin<<<grid, 256>>>(x, W_in, b_in, out);

    step_kernel<<<NCTA, NTHB, SMEM_BYTES>>>(W_hid, b_hid, alpha, init, out);
}

// round 15
// speedup vs baseline: 2.2214x; 1.0378x over previous
#include <cuda_runtime.h>
#include <cstdint>

#define NB    64
#define NT    1024
#define NIN   256
#define NH    512
#define NTHB  512
#define CLU   8                   // CTAs per cluster (col blocks)
#define NCLUS 16                  // clusters (batch groups, 4 batches each)
#define NCTA  (NCLUS * CLU)       // 128

// SMEM float offsets (dynamic)
// frs bufs: [512 k][8] = dup-packed {b0,b0,b1,b1,b2,b2,b3,b3} -> 16KB each
#define OFF_F0  0
#define OFF_F1  4096
#define OFF_RED 8192              // red[2]: [16 kt][4 b][72] floats each
#define RKT     288               // per-kt stride (4*72)
#define RBS     72                // per-batch stride (conflict-free fold)
#define REDSZ   (16 * RKT)        // one red buffer (4608 floats)
#define SMEM_FLOATS (OFF_RED + 2 * REDSZ)
#define SMEM_BYTES  (SMEM_FLOATS * 4)     // 69,632 B
#define TXPEER  2048u             // per-producer tx: 64 cols x 32 B

// ---------------- helpers -----------------------------------------------------
__device__ __forceinline__ uint64_t pk2(float x, float y) {
    uint64_t d; asm("mov.b64 %0, {%1, %2};" : "=l"(d) : "f"(x), "f"(y)); return d;
}
__device__ __forceinline__ void upk2(uint64_t d, float& x, float& y) {
    asm("mov.b64 {%0, %1}, %2;" : "=f"(x), "=f"(y) : "l"(d));
}
__device__ __forceinline__ uint64_t fma2(uint64_t a, uint64_t b, uint64_t c) {
    uint64_t d; asm("fma.rn.f32x2 %0, %1, %2, %3;" : "=l"(d) : "l"(a), "l"(b), "l"(c)); return d;
}
__device__ __forceinline__ uint32_t sm_u32(const void* p) {
    return (uint32_t)__cvta_generic_to_shared(p);
}

#define MBAR_INIT(addr, cnt) \
    asm volatile("mbarrier.init.shared.b64 [%0], %1;" :: "r"(addr), "r"(cnt) : "memory")
#define ARRIVE_EXPECT(addr, tx) \
    asm volatile("mbarrier.arrive.expect_tx.shared.b64 _, [%0], %1;" :: "r"(addr), "r"(tx) : "memory")
#define WAITP(addr, ph) do {                                                    \
    uint32_t _done;                                                             \
    do {                                                                        \
        asm volatile("{\n\t.reg .pred p;\n\t"                                   \
            "mbarrier.try_wait.parity.acquire.cta.shared::cta.b64 p, [%1], %2, 0x989680;\n\t" \
            "selp.b32 %0, 1, 0, p;\n\t}"                                        \
            : "=r"(_done) : "r"(addr), "r"(ph) : "memory");                     \
    } while (!_done);                                                           \
} while (0)
#define ST_ASYNC16(raddr, v0, v1, rmbar) \
    asm volatile("st.async.weak.shared::cluster.mbarrier::complete_tx::bytes.v2.b64 " \
                 "[%0], {%1, %2}, [%3];" :: "r"(raddr), "l"(v0), "l"(v1), "r"(rmbar) : "memory")
#define MAPA(dst, src, r) \
    asm volatile("mapa.shared::cluster.u32 %0, %1, %2;" : "=r"(dst) : "r"(src), "r"(r))
#define CLUSTER_SYNC_() do {                                          \
    asm volatile("barrier.cluster.arrive.aligned;" ::: "memory");     \
    asm volatile("barrier.cluster.wait.aligned;" ::: "memory");       \
} while (0)

// ---------------- Phase A: v_in = x @ W_in + b_in -> d_out (FFMA2) -----------
#define BM 64
#define BN 64
#define BK 16

__global__ __launch_bounds__(256) void gemm_vin(const float* __restrict__ A,
                                                const float* __restrict__ Bm,
                                                const float* __restrict__ bias,
                                                float* __restrict__ C) {
    __shared__ float    As[BK][BM + 4];
    __shared__ uint64_t Bs2[BK][BN / 2];
    const int tid = threadIdx.x;
    const int m0 = blockIdx.y * BM;
    const int n0 = blockIdx.x * BN;
    const int tx = tid & 15;
    const int ty = tid >> 4;

    uint64_t acc[4][2];
#pragma unroll
    for (int i = 0; i < 4; ++i) { acc[i][0] = 0; acc[i][1] = 0; }

    for (int k0 = 0; k0 < NIN; k0 += BK) {
#pragma unroll
        for (int i = tid; i < BM * BK / 4; i += 256) {
            int m = i >> 2, kq = i & 3;
            float4 v = *(const float4*)(A + (long)(m0 + m) * NIN + k0 + kq * 4);
            As[kq * 4 + 0][m] = v.x;
            As[kq * 4 + 1][m] = v.y;
            As[kq * 4 + 2][m] = v.z;
            As[kq * 4 + 3][m] = v.w;
        }
#pragma unroll
        for (int i = tid; i < BK * BN / 4; i += 256) {
            int kk = i >> 4, nq = i & 15;
            float4 v = *(const float4*)(Bm + (long)(k0 + kk) * NH + n0 + nq * 4);
            Bs2[kk][nq * 2 + 0] = pk2(v.x, v.y);
            Bs2[kk][nq * 2 + 1] = pk2(v.z, v.w);
        }
        __syncthreads();

#pragma unroll
        for (int kk = 0; kk < BK; ++kk) {
            float4 a4 = *(const float4*)(&As[kk][ty * 4]);
            ulonglong2 bp = *(const ulonglong2*)(&Bs2[kk][tx * 2]);
            uint64_t ad0 = pk2(a4.x, a4.x);
            uint64_t ad1 = pk2(a4.y, a4.y);
            uint64_t ad2 = pk2(a4.z, a4.z);
            uint64_t ad3 = pk2(a4.w, a4.w);
            acc[0][0] = fma2(ad0, bp.x, acc[0][0]);
            acc[0][1] = fma2(ad0, bp.y, acc[0][1]);
            acc[1][0] = fma2(ad1, bp.x, acc[1][0]);
            acc[1][1] = fma2(ad1, bp.y, acc[1][1]);
            acc[2][0] = fma2(ad2, bp.x, acc[2][0]);
            acc[2][1] = fma2(ad2, bp.y, acc[2][1]);
            acc[3][0] = fma2(ad3, bp.x, acc[3][0]);
            acc[3][1] = fma2(ad3, bp.y, acc[3][1]);
        }
        __syncthreads();
    }

#pragma unroll
    for (int i = 0; i < 4; ++i) {
        const int m = m0 + ty * 4 + i;
        const int n = n0 + tx * 4;
        float c0, c1, c2, c3;
        upk2(acc[i][0], c0, c1);
        upk2(acc[i][1], c2, c3);
        float4 o;
        o.x = c0 + bias[n + 0];
        o.y = c1 + bias[n + 1];
        o.z = c2 + bias[n + 2];
        o.w = c3 + bias[n + 3];
        *(float4*)(C + (long)m * NH + n) = o;
    }
}

// ---------------- Phase B: persistent recurrent kernel ----------------------
// 16 clusters x 8 CTAs; CTA = (4 batches) x (64 cols), 512 threads.
// W in REGISTERS (lane owns col-pair x 32 k = 32 u64). fr exchanged
// PRE-DUPLICATED via st.async + per-producer mbarriers.
// PIPELINED: red is double-buffered and the end-of-step syncthreads is GONE
// -- non-fold warps flow from publish straight to their next wait, so
// fold+send of step t overlaps compute of step t+1. WAR on red[x] is
// guaranteed by the publish-sync of the intervening step (fold(t-1) precedes
// sync(t) in program order; publish(t+1), same buffer, follows it).

__global__ __launch_bounds__(NTHB, 1) __cluster_dims__(CLU, 1, 1)
void step_kernel(const float* __restrict__ W_hid,
                 const float* __restrict__ b_hid,
                 const float* __restrict__ alpha,
                 const float* __restrict__ init_state,
                 float* __restrict__ out) {
    extern __shared__ float sh[];
    __shared__ uint64_t bars[2][CLU]; // [buf][producer rank]

    const int tid = threadIdx.x;
    uint32_t rank;
    asm("mov.u32 %0, %%cluster_ctarank;" : "=r"(rank));
    const int grp = blockIdx.x >> 3;      // 0..15
    const int B0  = grp * 4;
    const int C0  = (int)rank * 64;

    const int kt   = tid >> 5;            // warp = k-slice (32 k)
    const int lane = tid & 31;            // lane = col-pair (cols 2l, 2l+1)
    const int myprod = kt >> 1;           // producer peer of my k-slice
    // fold roles (tid < 256)
    const int eb = tid & 3;
    const int ec = tid >> 2;              // 0..63
    const int gb = B0 + eb;
    const int gc = C0 + ec;

    // ---- one-time: W col-pair slice into registers ----
    uint64_t wreg[32];
#pragma unroll
    for (int kk = 0; kk < 32; ++kk) {
        float2 wv = *(const float2*)(W_hid + (long)(kt * 32 + kk) * NH + C0 + 2 * lane);
        wreg[kk] = pk2(wv.x, wv.y);
    }

    // ---- barriers: 2 bufs x 8 producers, count=1, arm phase 0 w/ 2KB ----
    if (tid == 0) {
#pragma unroll
        for (int r = 0; r < CLU; ++r) {
            MBAR_INIT(sm_u32(&bars[0][r]), 1);
            MBAR_INIT(sm_u32(&bars[1][r]), 1);
            ARRIVE_EXPECT(sm_u32(&bars[0][r]), TXPEER);
            ARRIVE_EXPECT(sm_u32(&bars[1][r]), TXPEER);
        }
    }

    // ---- frs buf0 = relu(init_state), dup-packed [k][b0b0b1b1b2b2b3b3] ----
    {
        float* f0 = sh + OFF_F0;
        for (int i = tid; i < NH * 8; i += NTHB) {
            int k = i >> 3, b = (i & 7) >> 1;
            f0[i] = fmaxf(init_state[(long)(B0 + b) * NH + k], 0.f);
        }
    }

    float v = 0.f, al = 0.f, bh = 0.f, oma = 0.f;
    if (tid < 256) {
        v   = init_state[(long)gb * NH + gc];
        al  = alpha[gc];
        bh  = b_hid[gc];
        oma = 1.f - al;
    }
    __syncthreads();
    CLUSTER_SYNC_();    // barriers + armed state visible before any st.async

    const uint32_t mybar0 = sm_u32(&bars[0][myprod]);
    const uint32_t mybar1 = sm_u32(&bars[1][myprod]);

    int ph0 = 0, ph1 = 0;
    for (int t = 1; t <= NT; ++t) {
        const int pb = (t - 1) & 1;       // buffer holding fr(t-1)
        const int b  = t & 1;             // buffer receiving fr(t)
        float* red = sh + OFF_RED + b * REDSZ;   // publish buffer for step t

        long  oidx = 0;
        float vin  = 0.f;
        if (tid < 256) {
            oidx = ((long)gb * NT + (t - 1)) * NH + gc;
            vin  = out[oidx];             // DRAM prefetch
        }

        if (t >= 2) {
            const uint32_t ba = pb ? mybar1 : mybar0;
            const int ph = pb ? ph1 : ph0;
            WAITP(ba, ph);                // my producer's 2KB landed
            if (pb) ph1 ^= 1; else ph0 ^= 1;
            if ((kt & 1) == 0 && lane == 0) ARRIVE_EXPECT(ba, TXPEER);
        }

        // ---- compute: per k: 2 broadcast LDS.128 + 4 FFMA2 (W in regs) ----
        const float* fbase = sh + (pb ? OFF_F1 : OFF_F0) + kt * 256;
        uint64_t a0 = 0, a1 = 0, a2 = 0, a3 = 0;
#pragma unroll
        for (int kk = 0; kk < 32; ++kk) {
            ulonglong2 fA = *(const ulonglong2*)(fbase + kk * 8);      // {b0,b0},{b1,b1}
            ulonglong2 fB = *(const ulonglong2*)(fbase + kk * 8 + 4);  // {b2,b2},{b3,b3}
            a0 = fma2(fA.x, wreg[kk], a0);
            a1 = fma2(fA.y, wreg[kk], a1);
            a2 = fma2(fB.x, wreg[kk], a2);
            a3 = fma2(fB.y, wreg[kk], a3);
        }

        // ---- publish kt-partials into red[b] ----
        {
            float* rp = red + kt * RKT + 2 * lane;
            *(uint64_t*)(rp + 0 * RBS) = a0;
            *(uint64_t*)(rp + 1 * RBS) = a1;
            *(uint64_t*)(rp + 2 * RBS) = a2;
            *(uint64_t*)(rp + 3 * RBS) = a3;
        }
        __syncthreads();   // the ONLY per-step CTA sync

        // ---- fold + leaky update + scatter fr(t) (warps 0-7 only) ----
        if (tid < 256) {
            const float* rr = red + eb * RBS + ec;
            float s0 = rr[0 * RKT]  + rr[1 * RKT];
            float s1 = rr[2 * RKT]  + rr[3 * RKT];
            float s2 = rr[4 * RKT]  + rr[5 * RKT];
            float s3 = rr[6 * RKT]  + rr[7 * RKT];
            float s4 = rr[8 * RKT]  + rr[9 * RKT];
            float s5 = rr[10 * RKT] + rr[11 * RKT];
            float s6 = rr[12 * RKT] + rr[13 * RKT];
            float s7 = rr[14 * RKT] + rr[15 * RKT];
            float s  = ((s0 + s1) + (s2 + s3)) + ((s4 + s5) + (s6 + s7));

            v = oma * v + al * (s + bh + vin);
            const float fr = fmaxf(v, 0.f);

            if (t < NT) {                  // nobody consumes fr(NT)
                const float g0 = __shfl_sync(0xffffffffu, fr, 0, 4);
                const float g1 = __shfl_sync(0xffffffffu, fr, 1, 4);
                const float g2 = __shfl_sync(0xffffffffu, fr, 2, 4);
                const float g3 = __shfl_sync(0xffffffffu, fr, 3, 4);
                // eb==0 sends {b0,b0},{b1,b1}; eb==1 sends {b2,b2},{b3,b3}
                if (eb < 2) {
                    const uint64_t d0 = (eb == 0) ? pk2(g0, g0) : pk2(g2, g2);
                    const uint64_t d1 = (eb == 0) ? pk2(g1, g1) : pk2(g3, g3);
                    const uint32_t laddr =
                        sm_u32(sh + (b ? OFF_F1 : OFF_F0) + gc * 8 + eb * 4);
                    const uint32_t lbar = sm_u32(&bars[b][rank]);
#pragma unroll
                    for (int i = 0; i < CLU; ++i) {
                        const uint32_t r = (rank + (uint32_t)i) & 7;  // staggered
                        uint32_t ra, rb;
                        MAPA(ra, laddr, r);
                        MAPA(rb, lbar, r);
                        ST_ASYNC16(ra, d0, d1, rb);
                    }
                }
            }
            out[oidx] = fr;                // after sends: off critical path
        }
        // NO end-of-step syncthreads: warps 8-15 run ahead to next wait;
        // red WAR is covered by the publish-sync of the next step.
    }

    CLUSTER_SYNC_();                       // guard exit vs in-flight st.async
}

// ---------------- launch ----------------------------------------------------
extern "C" void kernel_launch(void* const* d_in, const int* in_sizes, int n_in,
                              void* d_out, int out_size) {
    const float* x     = (const float*)d_in[0];
    const float* init  = (const float*)d_in[1];
    const float* W_in  = (const float*)d_in[2];
    const float* b_in  = (const float*)d_in[3];
    const float* W_hid = (const float*)d_in[4];
    const float* b_hid = (const float*)d_in[5];
    const float* alpha = (const float*)d_in[6];
    float* out = (float*)d_out;

    cudaFuncSetAttribute(step_kernel,
                         cudaFuncAttributeMaxDynamicSharedMemorySize, SMEM_BYTES);

    dim3 grid(NH / BN, (NB * NT) / BM);    // (8, 1024)
    gemm_vin<<<grid, 256>>>(x, W_in, b_in, out);

    step_kernel<<<NCTA, NTHB, SMEM_BYTES>>>(W_hid, b_hid, alpha, init, out);
}

// round 16
// speedup vs baseline: 2.4154x; 1.0874x over previous
#include <cuda_runtime.h>
#include <cstdint>

#define NB    64
#define NT    1024
#define NIN   256
#define NH    512
#define NTHB  512
#define CLU   8                   // CTAs per cluster (col blocks)
#define NCLUS 8                   // clusters; each owns 8 batches (2 groups)
#define NCTA  (NCLUS * CLU)       // 64

// SMEM float offsets (dynamic)
// frs[group g][buf b]: [512 k][8] dup-packed {b0,b0,b1,b1,b2,b2,b3,b3} 16KB ea
#define FRS_BASE(g, b) (((g) * 2 + (b)) * 4096)
#define OFF_RED 16384             // red[2 seg]: [16 kt][4 b][72] floats each
#define RKT     288
#define RBS     72
#define REDSZ   (16 * RKT)
#define SMEM_FLOATS (OFF_RED + 2 * REDSZ)
#define SMEM_BYTES  (SMEM_FLOATS * 4)     // 102,400 B
#define TXPEER  2048u             // per-producer tx: 64 cols x 32 B

// ---------------- helpers -----------------------------------------------------
__device__ __forceinline__ uint64_t pk2(float x, float y) {
    uint64_t d; asm("mov.b64 %0, {%1, %2};" : "=l"(d) : "f"(x), "f"(y)); return d;
}
__device__ __forceinline__ void upk2(uint64_t d, float& x, float& y) {
    asm("mov.b64 {%0, %1}, %2;" : "=f"(x), "=f"(y) : "l"(d));
}
__device__ __forceinline__ uint64_t fma2(uint64_t a, uint64_t b, uint64_t c) {
    uint64_t d; asm("fma.rn.f32x2 %0, %1, %2, %3;" : "=l"(d) : "l"(a), "l"(b), "l"(c)); return d;
}
__device__ __forceinline__ uint32_t sm_u32(const void* p) {
    return (uint32_t)__cvta_generic_to_shared(p);
}

#define MBAR_INIT(addr, cnt) \
    asm volatile("mbarrier.init.shared.b64 [%0], %1;" :: "r"(addr), "r"(cnt) : "memory")
#define ARRIVE_EXPECT(addr, tx) \
    asm volatile("mbarrier.arrive.expect_tx.shared.b64 _, [%0], %1;" :: "r"(addr), "r"(tx) : "memory")
#define WAITP(addr, ph) do {                                                    \
    uint32_t _done;                                                             \
    do {                                                                        \
        asm volatile("{\n\t.reg .pred p;\n\t"                                   \
            "mbarrier.try_wait.parity.acquire.cta.shared::cta.b64 p, [%1], %2, 0x989680;\n\t" \
            "selp.b32 %0, 1, 0, p;\n\t}"                                        \
            : "=r"(_done) : "r"(addr), "r"(ph) : "memory");                     \
    } while (!_done);                                                           \
} while (0)
#define ST_ASYNC16(raddr, v0, v1, rmbar) \
    asm volatile("st.async.weak.shared::cluster.mbarrier::complete_tx::bytes.v2.b64 " \
                 "[%0], {%1, %2}, [%3];" :: "r"(raddr), "l"(v0), "l"(v1), "r"(rmbar) : "memory")
#define MAPA(dst, src, r) \
    asm volatile("mapa.shared::cluster.u32 %0, %1, %2;" : "=r"(dst) : "r"(src), "r"(r))
#define CLUSTER_SYNC_() do {                                          \
    asm volatile("barrier.cluster.arrive.aligned;" ::: "memory");     \
    asm volatile("barrier.cluster.wait.aligned;" ::: "memory");       \
} while (0)

// ---------------- Phase A: v_in = x @ W_in + b_in -> d_out (FFMA2) -----------
#define BM 64
#define BN 64
#define BK 16

__global__ __launch_bounds__(256) void gemm_vin(const float* __restrict__ A,
                                                const float* __restrict__ Bm,
                                                const float* __restrict__ bias,
                                                float* __restrict__ C) {
    __shared__ float    As[BK][BM + 4];
    __shared__ uint64_t Bs2[BK][BN / 2];
    const int tid = threadIdx.x;
    const int m0 = blockIdx.y * BM;
    const int n0 = blockIdx.x * BN;
    const int tx = tid & 15;
    const int ty = tid >> 4;

    uint64_t acc[4][2];
#pragma unroll
    for (int i = 0; i < 4; ++i) { acc[i][0] = 0; acc[i][1] = 0; }

    for (int k0 = 0; k0 < NIN; k0 += BK) {
#pragma unroll
        for (int i = tid; i < BM * BK / 4; i += 256) {
            int m = i >> 2, kq = i & 3;
            float4 v = *(const float4*)(A + (long)(m0 + m) * NIN + k0 + kq * 4);
            As[kq * 4 + 0][m] = v.x;
            As[kq * 4 + 1][m] = v.y;
            As[kq * 4 + 2][m] = v.z;
            As[kq * 4 + 3][m] = v.w;
        }
#pragma unroll
        for (int i = tid; i < BK * BN / 4; i += 256) {
            int kk = i >> 4, nq = i & 15;
            float4 v = *(const float4*)(Bm + (long)(k0 + kk) * NH + n0 + nq * 4);
            Bs2[kk][nq * 2 + 0] = pk2(v.x, v.y);
            Bs2[kk][nq * 2 + 1] = pk2(v.z, v.w);
        }
        __syncthreads();

#pragma unroll
        for (int kk = 0; kk < BK; ++kk) {
            float4 a4 = *(const float4*)(&As[kk][ty * 4]);
            ulonglong2 bp = *(const ulonglong2*)(&Bs2[kk][tx * 2]);
            uint64_t ad0 = pk2(a4.x, a4.x);
            uint64_t ad1 = pk2(a4.y, a4.y);
            uint64_t ad2 = pk2(a4.z, a4.z);
            uint64_t ad3 = pk2(a4.w, a4.w);
            acc[0][0] = fma2(ad0, bp.x, acc[0][0]);
            acc[0][1] = fma2(ad0, bp.y, acc[0][1]);
            acc[1][0] = fma2(ad1, bp.x, acc[1][0]);
            acc[1][1] = fma2(ad1, bp.y, acc[1][1]);
            acc[2][0] = fma2(ad2, bp.x, acc[2][0]);
            acc[2][1] = fma2(ad2, bp.y, acc[2][1]);
            acc[3][0] = fma2(ad3, bp.x, acc[3][0]);
            acc[3][1] = fma2(ad3, bp.y, acc[3][1]);
        }
        __syncthreads();
    }

#pragma unroll
    for (int i = 0; i < 4; ++i) {
        const int m = m0 + ty * 4 + i;
        const int n = n0 + tx * 4;
        float c0, c1, c2, c3;
        upk2(acc[i][0], c0, c1);
        upk2(acc[i][1], c2, c3);
        float4 o;
        o.x = c0 + bias[n + 0];
        o.y = c1 + bias[n + 1];
        o.z = c2 + bias[n + 2];
        o.w = c3 + bias[n + 3];
        *(float4*)(C + (long)m * NH + n) = o;
    }
}

// ---------------- Phase B: persistent recurrent kernel ----------------------
// 8 clusters x 8 CTAs; cluster owns 8 batches = groups A/B (4 each); CTA =
// 64 cols, W in REGISTERS (lane owns col-pair x 32 k). Each step runs
// segment A then segment B: A's exchange (port drain + transit) hides under
// all of segment B, so waits hit already-fired barriers. st.async +
// per-producer mbarriers, dup-packed sends, red double-buffered by segment.

__global__ __launch_bounds__(NTHB, 1) __cluster_dims__(CLU, 1, 1)
void step_kernel(const float* __restrict__ W_hid,
                 const float* __restrict__ b_hid,
                 const float* __restrict__ alpha,
                 const float* __restrict__ init_state,
                 float* __restrict__ out) {
    extern __shared__ float sh[];
    __shared__ uint64_t bars[2][2][CLU];   // [group][buf][producer rank]

    const int tid = threadIdx.x;
    uint32_t rank;
    asm("mov.u32 %0, %%cluster_ctarank;" : "=r"(rank));
    const int grp = blockIdx.x >> 3;       // 0..7 (batch super-group)
    const int B0A = grp * 8;
    const int B0B = grp * 8 + 4;
    const int C0  = (int)rank * 64;

    const int kt     = tid >> 5;           // warp = k-slice (32 k)
    const int lane   = tid & 31;           // lane = col-pair
    const int myprod = kt >> 1;            // producer peer of my k-slice
    // fold roles (tid < 256)
    const int eb = tid & 3;
    const int ec = tid >> 2;               // 0..63
    const int gc = C0 + ec;

    // ---- one-time: W col-pair slice into registers ----
    uint64_t wreg[32];
#pragma unroll
    for (int kk = 0; kk < 32; ++kk) {
        float2 wv = *(const float2*)(W_hid + (long)(kt * 32 + kk) * NH + C0 + 2 * lane);
        wreg[kk] = pk2(wv.x, wv.y);
    }

    // ---- barriers: 2 groups x 2 bufs x 8 producers; arm phase 0 w/ 2KB ----
    if (tid == 0) {
#pragma unroll
        for (int g = 0; g < 2; ++g)
#pragma unroll
            for (int bb = 0; bb < 2; ++bb)
#pragma unroll
                for (int r = 0; r < CLU; ++r) {
                    MBAR_INIT(sm_u32(&bars[g][bb][r]), 1);
                    ARRIVE_EXPECT(sm_u32(&bars[g][bb][r]), TXPEER);
                }
    }

    // ---- buf0 of both groups = relu(init_state), dup-packed ----
    for (int i = tid; i < NH * 8; i += NTHB) {
        int k = i >> 3, b = (i & 7) >> 1;
        sh[FRS_BASE(0, 0) + i] = fmaxf(init_state[(long)(B0A + b) * NH + k], 0.f);
        sh[FRS_BASE(1, 0) + i] = fmaxf(init_state[(long)(B0B + b) * NH + k], 0.f);
    }

    float vA = 0.f, vB = 0.f, al = 0.f, bh = 0.f, oma = 0.f;
    if (tid < 256) {
        vA  = init_state[(long)(B0A + eb) * NH + gc];
        vB  = init_state[(long)(B0B + eb) * NH + gc];
        al  = alpha[gc];
        bh  = b_hid[gc];
        oma = 1.f - al;
    }
    __syncthreads();
    CLUSTER_SYNC_();    // barriers + armed state visible before any st.async

    int phA0 = 0, phA1 = 0, phB0 = 0, phB1 = 0;

    // one segment: wait, compute, publish, sync, fold, send for group g
    auto segment = [&](int t, int g, int B0g, float& vG, int& phb0, int& phb1) {
        const int pb = (t - 1) & 1;        // buffer holding fr_g(t-1)
        const int b  = t & 1;              // buffer receiving fr_g(t)
        float* red = sh + OFF_RED + g * REDSZ;

        long  oidx = 0;
        float vin  = 0.f;
        if (tid < 256) {
            oidx = ((long)(B0g + eb) * NT + (t - 1)) * NH + gc;
            vin  = out[oidx];              // DRAM prefetch
        }

        if (t >= 2) {
            const uint32_t ba = sm_u32(&bars[g][pb][myprod]);
            const int ph = pb ? phb1 : phb0;
            WAITP(ba, ph);                 // my producer's 2KB landed
            if (pb) phb1 ^= 1; else phb0 ^= 1;
            if ((kt & 1) == 0 && lane == 0) ARRIVE_EXPECT(ba, TXPEER);
        }

        // ---- compute: per k: 2 broadcast LDS.128 + 4 FFMA2 (W in regs) ----
        const float* fbase = sh + FRS_BASE(g, pb) + kt * 256;
        uint64_t a0 = 0, a1 = 0, a2 = 0, a3 = 0;
#pragma unroll
        for (int kk = 0; kk < 32; ++kk) {
            ulonglong2 fA = *(const ulonglong2*)(fbase + kk * 8);
            ulonglong2 fB = *(const ulonglong2*)(fbase + kk * 8 + 4);
            a0 = fma2(fA.x, wreg[kk], a0);
            a1 = fma2(fA.y, wreg[kk], a1);
            a2 = fma2(fB.x, wreg[kk], a2);
            a3 = fma2(fB.y, wreg[kk], a3);
        }

        // ---- publish kt-partials into red[g] ----
        {
            float* rp = red + kt * RKT + 2 * lane;
            *(uint64_t*)(rp + 0 * RBS) = a0;
            *(uint64_t*)(rp + 1 * RBS) = a1;
            *(uint64_t*)(rp + 2 * RBS) = a2;
            *(uint64_t*)(rp + 3 * RBS) = a3;
        }
        __syncthreads();   // the ONLY per-segment CTA sync

        // ---- fold + leaky update + scatter fr_g(t) (warps 0-7) ----
        if (tid < 256) {
            const float* rr = red + eb * RBS + ec;
            float s0 = rr[0 * RKT]  + rr[1 * RKT];
            float s1 = rr[2 * RKT]  + rr[3 * RKT];
            float s2 = rr[4 * RKT]  + rr[5 * RKT];
            float s3 = rr[6 * RKT]  + rr[7 * RKT];
            float s4 = rr[8 * RKT]  + rr[9 * RKT];
            float s5 = rr[10 * RKT] + rr[11 * RKT];
            float s6 = rr[12 * RKT] + rr[13 * RKT];
            float s7 = rr[14 * RKT] + rr[15 * RKT];
            float s  = ((s0 + s1) + (s2 + s3)) + ((s4 + s5) + (s6 + s7));

            vG = oma * vG + al * (s + bh + vin);
            const float fr = fmaxf(vG, 0.f);

            if (t < NT) {                  // nobody consumes fr(NT)
                const float g0 = __shfl_sync(0xffffffffu, fr, 0, 4);
                const float g1 = __shfl_sync(0xffffffffu, fr, 1, 4);
                const float g2 = __shfl_sync(0xffffffffu, fr, 2, 4);
                const float g3 = __shfl_sync(0xffffffffu, fr, 3, 4);
                if (eb < 2) {
                    const uint64_t d0 = (eb == 0) ? pk2(g0, g0) : pk2(g2, g2);
                    const uint64_t d1 = (eb == 0) ? pk2(g1, g1) : pk2(g3, g3);
                    const uint32_t laddr =
                        sm_u32(sh + FRS_BASE(g, b) + gc * 8 + eb * 4);
                    const uint32_t lbar = sm_u32(&bars[g][b][rank]);
#pragma unroll
                    for (int i = 0; i < CLU; ++i) {
                        const uint32_t r = (rank + (uint32_t)i) & 7;
                        uint32_t ra, rb;
                        MAPA(ra, laddr, r);
                        MAPA(rb, lbar, r);
                        ST_ASYNC16(ra, d0, d1, rb);
                    }
                }
            }
            out[oidx] = fr;                // off critical path
        }
        // no tail sync: red[g] WAR covered by the other segment's publish-sync
    };

    for (int t = 1; t <= NT; ++t) {
        segment(t, 0, B0A, vA, phA0, phA1);   // A's exchange hides under B
        segment(t, 1, B0B, vB, phB0, phB1);   // B's hides under next A
    }

    CLUSTER_SYNC_();                       // guard exit vs in-flight st.async
}

// ---------------- launch ----------------------------------------------------
extern "C" void kernel_launch(void* const* d_in, const int* in_sizes, int n_in,
                              void* d_out, int out_size) {
    const float* x     = (const float*)d_in[0];
    const float* init  = (const float*)d_in[1];
    const float* W_in  = (const float*)d_in[2];
    const float* b_in  = (const float*)d_in[3];
    const float* W_hid = (const float*)d_in[4];
    const float* b_hid = (const float*)d_in[5];
    const float* alpha = (const float*)d_in[6];
    float* out = (float*)d_out;

    cudaFuncSetAttribute(step_kernel,
                         cudaFuncAttributeMaxDynamicSharedMemorySize, SMEM_BYTES);

    dim3 grid(NH / BN, (NB * NT) / BM);    // (8, 1024)
    gemm_vin<<<grid, 256>>>(x, W_in, b_in, out);

    step_kernel<<<NCTA, NTHB, SMEM_BYTES>>>(W_hid, b_hid, alpha, init, out);
}